// round 17
// baseline (speedup 1.0000x reference)
#include <cuda_runtime.h>
#include <cuda_fp16.h>
#include <cstdint>

#define FULL_MASK 0xffffffffu

// pack two f32 -> f16x2 (hi arg in upper 16 bits = .y, lo arg in lower = .x)
__device__ __forceinline__ __half2 pack_h2(float hi, float lo) {
    uint32_t r; asm("cvt.rn.f16x2.f32 %0, %1, %2;" : "=r"(r) : "f"(hi), "f"(lo));
    return *reinterpret_cast<__half2*>(&r);
}
__device__ __forceinline__ __half2 tanh_h2(__half2 v) {
    uint32_t u = *reinterpret_cast<uint32_t*>(&v);
    asm("tanh.approx.f16x2 %0, %1;" : "=r"(u) : "r"(u));
    return *reinterpret_cast<__half2*>(&u);
}
__device__ __forceinline__ uint32_t h2_raw(__half2 v) {
    return *reinterpret_cast<uint32_t*>(&v);
}
__device__ __forceinline__ uint32_t pack_f16(float hi, float lo) {
    uint32_t r; asm("cvt.rn.f16x2.f32 %0, %1, %2;" : "=r"(r) : "f"(hi), "f"(lo));
    return r;
}

// D[16,8] += A[16,16] * B[16,8], f16 in, f32 accum. Row-major A, col-major B.
__device__ __forceinline__ void mma16816(float4& d,
                                         uint32_t a0, uint32_t a1,
                                         uint32_t a2, uint32_t a3,
                                         uint32_t b0, uint32_t b1) {
    asm("mma.sync.aligned.m16n8k16.row.col.f32.f16.f16.f32 "
        "{%0,%1,%2,%3}, {%4,%5,%6,%7}, {%8,%9}, {%0,%1,%2,%3};"
        : "+f"(d.x), "+f"(d.y), "+f"(d.z), "+f"(d.w)
        : "r"(a0), "r"(a1), "r"(a2), "r"(a3), "r"(b0), "r"(b1));
}

// H=32, 4H=128 gates (g-major: n = 32*g + u), I=1, T=512, B=8192.
//
// R17: WARP-AUTONOMOUS (no inter-warp exchange, no __syncthreads on the
// recurrence path). One warp = 16 batches, owning ALL 128 gate columns:
// D tiles j = 4g + jj (gate g, unit slice jj), 16 tiles/step.
// M16 rows 0-7 = batches base..+7 (D .x/.y), rows 8-15 = base+8..+15
// (.z/.w). Lane l: gr=l>>2, gc=l&3 -> cells (units 8jj+2gc,+1) x 2 grps.
//
// Key property: the h pair a lane computes for tile jj/grp IS its own
// m16n8k16 A-operand word next step: kfrag = jj>>1, word = (jj&1 ? a2/a3
// : a0/a1), grp0 -> a0/a2, grp1 -> a1/a3. h single f16 (R15),
// activations f16x2 end-to-end (R16), c in fp32. New A-words staged in
// nh[][] and committed AFTER all 16 tiles (R9 WAR lesson).
//
// 32 MMAs + 40 MUFU per warp-step. Weights BW single f16 in registers;
// x-gate coefficient table wb4 in smem (1 LDS.128 per tile per step).
// 1-warp CTAs: grid 512 x block 32, ~3.46 warps/SM spread over SMSPs.

__global__ void __launch_bounds__(32, 16) lstm_mma_kernel(
    const float* __restrict__ x,      // [B, 512]
    const float* __restrict__ W_ih,   // [128]
    const float* __restrict__ W_hh,   // [128, 32]
    const float* __restrict__ b_ih,   // [128]
    const float* __restrict__ b_hh,   // [128]
    const float* __restrict__ W_lin,  // [32]
    const float* __restrict__ b_lin,  // [1]
    float* __restrict__ out)          // [B]
{
    // wb4[tile*4 + gc] = (PS*W_ih[m], PS*bias[m], PS*W_ih[m+1], PS*bias[m+1]),
    // m = 32*(tile>>2) + 8*(tile&3) + 2*gc
    __shared__ __align__(16) float4 wb4[64];
    __shared__ __align__(16) float xs[16][36];   // [batch][step] padded

    const int l  = threadIdx.x;
    const int gr = l >> 2;
    const int gc = l & 3;

    for (int i = l; i < 64; i += 32) {
        const int tile = i >> 2, gcx = i & 3;
        const int g = tile >> 2;
        const float ps = (g == 2) ? 1.0f : 0.5f;
        const int m = 32 * g + 8 * (tile & 3) + 2 * gcx;
        wb4[i] = make_float4(ps * W_ih[m],     ps * (b_ih[m]     + b_hh[m]),
                             ps * W_ih[m + 1], ps * (b_ih[m + 1] + b_hh[m + 1]));
    }

    // ---- per-lane weight fragments (single f16): BW[tile][kfrag] ----
    uint2 BW[16][2];
    #pragma unroll
    for (int j = 0; j < 16; ++j) {
        const int g = j >> 2;
        const float ps = (g == 2) ? 1.0f : 0.5f;
        const int n = 8 * j + gr;                  // B row for this lane
        const float* wr = W_hh + n * 32;
        #pragma unroll
        for (int kk = 0; kk < 2; ++kk) {
            const int k0 = kk * 16 + 2 * gc;
            BW[j][kk] = make_uint2(
                pack_f16(ps * wr[k0 + 1], ps * wr[k0]),
                pack_f16(ps * wr[k0 + 9], ps * wr[k0 + 8]));
        }
    }
    __syncwarp();

    const int base = blockIdx.x * 16;
    // x staging: lane loads batch l>>1, steps 16*(l&1)..+15 per 32-chunk
    const float* xb = x + (size_t)(base + (l >> 1)) * 512 + 16 * (l & 1);
    float* xw = &xs[l >> 1][16 * (l & 1)];

    // A-operand words per kfrag: uint4(a0,a1,a2,a3)
    //   a0 = h(jj=2kf, grp0), a1 = h(jj=2kf, grp1),
    //   a2 = h(jj=2kf+1, grp0), a3 = h(jj=2kf+1, grp1)
    uint4 Aw[2];
    Aw[0] = make_uint4(0u, 0u, 0u, 0u);
    Aw[1] = make_uint4(0u, 0u, 0u, 0u);

    float cc[4][2][2] = {};          // [jj][grp][e], fp32
    const __half2 H05 = __float2half2_rn(0.5f);

    for (int t0 = 0; t0 < 512; t0 += 32) {
        const float4 v0 = *reinterpret_cast<const float4*>(xb + t0);
        const float4 v1 = *reinterpret_cast<const float4*>(xb + t0 + 4);
        const float4 v2 = *reinterpret_cast<const float4*>(xb + t0 + 8);
        const float4 v3 = *reinterpret_cast<const float4*>(xb + t0 + 12);
        __syncwarp();                 // prior-chunk xs reads done
        *reinterpret_cast<float4*>(xw)      = v0;
        *reinterpret_cast<float4*>(xw + 4)  = v1;
        *reinterpret_cast<float4*>(xw + 8)  = v2;
        *reinterpret_cast<float4*>(xw + 12) = v3;
        __syncwarp();                 // stores visible

        #pragma unroll 1
        for (int tc = 0; tc < 32; ++tc) {
            const float xtA = xs[gr][tc];
            const float xtB = xs[gr + 8][tc];

            uint32_t nh0[4], nh1[4];  // new h words per jj (grp0, grp1)

            #pragma unroll
            for (int jj = 0; jj < 4; ++jj) {
                float4 d[4];
                #pragma unroll
                for (int g = 0; g < 4; ++g) {
                    const int j = 4 * g + jj;
                    const float4 q = wb4[j * 4 + gc];   // LDS.128
                    d[g].x = fmaf(xtA, q.x, q.y);
                    d[g].y = fmaf(xtA, q.z, q.w);
                    d[g].z = fmaf(xtB, q.x, q.y);
                    d[g].w = fmaf(xtB, q.z, q.w);
                    mma16816(d[g], Aw[0].x, Aw[0].y, Aw[0].z, Aw[0].w,
                             BW[j][0].x, BW[j][0].y);
                    mma16816(d[g], Aw[1].x, Aw[1].y, Aw[1].z, Aw[1].w,
                             BW[j][1].x, BW[j][1].y);
                }
                // ---- activations, f16x2 end-to-end, per grp ----
                #pragma unroll
                for (int grp = 0; grp < 2; ++grp) {
                    const float p0i = grp ? d[0].z : d[0].x;
                    const float p1i = grp ? d[0].w : d[0].y;
                    const float p0f = grp ? d[1].z : d[1].x;
                    const float p1f = grp ? d[1].w : d[1].y;
                    const float p0g = grp ? d[2].z : d[2].x;
                    const float p1g = grp ? d[2].w : d[2].y;
                    const float p0o = grp ? d[3].z : d[3].x;
                    const float p1o = grp ? d[3].w : d[3].y;

                    const __half2 Ti = tanh_h2(pack_h2(p1i, p0i));
                    const __half2 Tf = tanh_h2(pack_h2(p1f, p0f));
                    const __half2 Tg = tanh_h2(pack_h2(p1g, p0g));
                    const __half2 To = tanh_h2(pack_h2(p1o, p0o));

                    const __half2 si = __hfma2(H05, Ti, H05);
                    const __half2 sf = __hfma2(H05, Tf, H05);
                    const __half2 so = __hfma2(H05, To, H05);
                    const __half2 ig = __hmul2(si, Tg);

                    const float2 igf = __half22float2(ig);
                    const float2 sff = __half22float2(sf);
                    cc[jj][grp][0] = fmaf(sff.x, cc[jj][grp][0], igf.x);
                    cc[jj][grp][1] = fmaf(sff.y, cc[jj][grp][1], igf.y);

                    const __half2 tcp =
                        tanh_h2(pack_h2(cc[jj][grp][1], cc[jj][grp][0]));
                    const uint32_t hw = h2_raw(__hmul2(so, tcp));
                    if (grp == 0) nh0[jj] = hw; else nh1[jj] = hw;
                }
            }

            // commit new A-words AFTER all 16 tiles consumed h_{t-1}
            Aw[0] = make_uint4(nh0[0], nh1[0], nh0[1], nh1[1]);
            Aw[1] = make_uint4(nh0[2], nh1[2], nh0[3], nh1[3]);
        }
    }

    // ---- epilogue: out[b] = dot(h, W_lin) + b_lin (in-warp reduction) ----
    float vA = 0.0f, vB = 0.0f;
    #pragma unroll
    for (int jj = 0; jj < 4; ++jj) {
        const uint32_t w0 = (jj & 1) ? ((jj >> 1) ? Aw[1].z : Aw[0].z)
                                     : ((jj >> 1) ? Aw[1].x : Aw[0].x);
        const uint32_t w1 = (jj & 1) ? ((jj >> 1) ? Aw[1].w : Aw[0].w)
                                     : ((jj >> 1) ? Aw[1].y : Aw[0].y);
        const __half2 hA = *reinterpret_cast<const __half2*>(&w0);
        const __half2 hB = *reinterpret_cast<const __half2*>(&w1);
        const float2 fA = __half22float2(hA);
        const float2 fB = __half22float2(hB);
        const float wl0 = W_lin[8 * jj + 2 * gc];
        const float wl1 = W_lin[8 * jj + 2 * gc + 1];
        vA = fmaf(fA.x, wl0, vA); vA = fmaf(fA.y, wl1, vA);
        vB = fmaf(fB.x, wl0, vB); vB = fmaf(fB.y, wl1, vB);
    }
    vA += __shfl_xor_sync(FULL_MASK, vA, 1);
    vA += __shfl_xor_sync(FULL_MASK, vA, 2);
    vB += __shfl_xor_sync(FULL_MASK, vB, 1);
    vB += __shfl_xor_sync(FULL_MASK, vB, 2);
    if (gc == 0) {
        out[base + gr]     = vA + b_lin[0];
        out[base + gr + 8] = vB + b_lin[0];
    }
}

extern "C" void kernel_launch(void* const* d_in, const int* in_sizes, int n_in,
                              void* d_out, int out_size) {
    const float* x     = (const float*)d_in[0];
    const float* W_ih  = (const float*)d_in[1];
    const float* W_hh  = (const float*)d_in[2];
    const float* b_ih  = (const float*)d_in[3];
    const float* b_hh  = (const float*)d_in[4];
    const float* W_lin = (const float*)d_in[5];
    const float* b_lin = (const float*)d_in[6];
    float* out = (float*)d_out;

    // 8192 batches / 16 per warp = 512 single-warp CTAs.
    lstm_mma_kernel<<<512, 32>>>(x, W_ih, W_hh, b_ih, b_hh, W_lin, b_lin, out);
}